// round 4
// baseline (speedup 1.0000x reference)
#include <cuda_runtime.h>
#include <cuda_fp16.h>
#include <cstdint>

// Problem constants (fixed by the dataset)
#define IN_F   4096
#define OUT_F  11008
#define GROUPS 32       // IN_F / 128
#define BM 128
#define BN 128
#define BK 64           // halves per k-tile
#define STAGES 3
#define STAGE_A_BYTES (BM * BK * 2)                // 16384
#define STAGE_BYTES   (BM * BK * 2 + BN * BK * 2)  // 32768
#define KT (IN_F / BK)  // 64

// Dequantized weights, fp16, [OUT_F][IN_F] row-major (K contiguous).
__device__ __half g_W[(size_t)OUT_F * IN_F];
// Activations converted to fp16, [M][IN_F] (M = 4096 for this dataset).
__device__ __half g_X[(size_t)4096 * IN_F];

// ---------------------------------------------------------------------------
// Convert x (float32, fp16-valued) -> fp16 in g_X. 8 elements / thread.
// ---------------------------------------------------------------------------
__global__ void convert_kernel(const float4* __restrict__ xin, int n) {
    int i = (blockIdx.x * blockDim.x + threadIdx.x) * 8;
    if (i >= n) return;
    float4 a = xin[i / 4];
    float4 b = xin[i / 4 + 1];
    __half2 h[4];
    h[0] = __floats2half2_rn(a.x, a.y);
    h[1] = __floats2half2_rn(a.z, a.w);
    h[2] = __floats2half2_rn(b.x, b.y);
    h[3] = __floats2half2_rn(b.z, b.w);
    *reinterpret_cast<uint4*>(g_X + i) = *reinterpret_cast<uint4*>(h);
}

// ---------------------------------------------------------------------------
// Dequant: qweight [O][K/2] int32 (one byte/word, two nibbles, low first)
//          qzeros  [O][GROUPS/2] int32, scales [O][GROUPS] float32
// Each thread: 4 packed int32 -> 8 fp16 weights (one uint4 store).
// All 8 weights share one group (8 | 64).
// ---------------------------------------------------------------------------
__global__ void dequant_kernel(const int4* __restrict__ qw,
                               const float* __restrict__ scales,
                               const int* __restrict__ qz) {
    const int JP = IN_F / 8;  // 512 int4-chunks per output row
    int idx = blockIdx.x * blockDim.x + threadIdx.x;
    if (idx >= OUT_F * JP) return;

    int o  = idx / JP;
    int jq = idx - o * JP;
    int g  = jq >> 4;           // group = (jq*8)/128

    int4 v = qw[idx];
    int zb = qz[o * (GROUPS / 2) + (g >> 1)];
    int z  = (g & 1) ? ((zb >> 4) & 15) : (zb & 15);
    float s = scales[o * GROUPS + g];

    int q[4] = {v.x, v.y, v.z, v.w};
    __half2 h[4];
#pragma unroll
    for (int t = 0; t < 4; t++) {
        float w0 = (float)((q[t] & 15) - z) * s;
        float w1 = (float)(((q[t] >> 4) & 15) - z) * s;
        h[t] = __floats2half2_rn(w0, w1);
    }
    *reinterpret_cast<uint4*>(g_W + (size_t)idx * 8) = *reinterpret_cast<uint4*>(h);
}

// ---------------------------------------------------------------------------
// GEMM: C[M][OUT_F] (f32) = A[M][IN_F] (f16) * W^T
// TN mma.sync.m16n8k16, BM=128 BN=128 BK=64, 3-stage cp.async,
// SW128-swizzled smem, 8 warps (2x4), warp tile 64x32.
// ---------------------------------------------------------------------------
__device__ __forceinline__ uint32_t sw128(uint32_t o) {
    return o ^ ((o >> 3) & 0x70);
}

__device__ __forceinline__ void cp_async16(uint32_t saddr, const void* gptr) {
    asm volatile("cp.async.cg.shared.global [%0], [%1], 16;\n"
                 :: "r"(saddr), "l"(gptr) : "memory");
}

__device__ __forceinline__ void load_tiles(uint32_t sA, uint32_t sB,
                                           const __half* __restrict__ Ag,
                                           const __half* __restrict__ Bg,
                                           int m0, int n0, int k0, int tid) {
#pragma unroll
    for (int i = 0; i < 4; i++) {
        int chunk = tid + i * 256;
        int r = chunk >> 3;
        int c = chunk & 7;
        uint32_t off = sw128((uint32_t)(r * 128 + c * 16));
        cp_async16(sA + off, Ag + (size_t)(m0 + r) * IN_F + k0 + c * 8);
    }
#pragma unroll
    for (int i = 0; i < 4; i++) {
        int chunk = tid + i * 256;
        int r = chunk >> 3;
        int c = chunk & 7;
        uint32_t off = sw128((uint32_t)(r * 128 + c * 16));
        cp_async16(sB + off, Bg + (size_t)(n0 + r) * IN_F + k0 + c * 8);
    }
}

__global__ void __launch_bounds__(256)
gemm_kernel(float* __restrict__ C) {
    extern __shared__ char smem[];
    const __half* __restrict__ A = g_X;
    const __half* __restrict__ B = g_W;

    const int tid  = threadIdx.x;
    const int lane = tid & 31;
    const int warp = tid >> 5;
    const int wm   = warp & 1;
    const int wn   = warp >> 1;
    const int m0   = blockIdx.x * BM;
    const int n0   = blockIdx.y * BN;

    uint32_t sbase = (uint32_t)__cvta_generic_to_shared(smem);

    float acc[4][4][4];
#pragma unroll
    for (int i = 0; i < 4; i++)
#pragma unroll
        for (int j = 0; j < 4; j++)
#pragma unroll
            for (int k = 0; k < 4; k++) acc[i][j][k] = 0.0f;

#pragma unroll
    for (int s = 0; s < STAGES - 1; s++) {
        uint32_t sA = sbase + s * STAGE_BYTES;
        load_tiles(sA, sA + STAGE_A_BYTES, A, B, m0, n0, s * BK, tid);
        asm volatile("cp.async.commit_group;\n" ::: "memory");
    }

    for (int kt = 0; kt < KT; kt++) {
        asm volatile("cp.async.wait_group 1;\n" ::: "memory");
        __syncthreads();

        int kn = kt + STAGES - 1;
        if (kn < KT) {
            uint32_t sA = sbase + (kn % STAGES) * STAGE_BYTES;
            load_tiles(sA, sA + STAGE_A_BYTES, A, B, m0, n0, kn * BK, tid);
        }
        asm volatile("cp.async.commit_group;\n" ::: "memory");

        const int stage = kt % STAGES;
        uint32_t sA = sbase + stage * STAGE_BYTES;
        uint32_t sB = sA + STAGE_A_BYTES;

#pragma unroll
        for (int ks = 0; ks < 4; ks++) {
            uint32_t a[4][4];
            uint32_t b[4][2];
            const int cb = ks * 32 + ((lane >> 4) << 4);

#pragma unroll
            for (int mf = 0; mf < 4; mf++) {
                int r = wm * 64 + mf * 16 + (lane & 15);
                uint32_t addr = sA + sw128((uint32_t)(r * 128 + cb));
                asm volatile(
                    "ldmatrix.sync.aligned.m8n8.x4.shared.b16 {%0,%1,%2,%3}, [%4];\n"
                    : "=r"(a[mf][0]), "=r"(a[mf][1]), "=r"(a[mf][2]), "=r"(a[mf][3])
                    : "r"(addr));
            }
#pragma unroll
            for (int p = 0; p < 2; p++) {
                int r = wn * 32 + p * 16 + (lane & 15);
                uint32_t addr = sB + sw128((uint32_t)(r * 128 + cb));
                uint32_t r0, r1, r2, r3;
                asm volatile(
                    "ldmatrix.sync.aligned.m8n8.x4.shared.b16 {%0,%1,%2,%3}, [%4];\n"
                    : "=r"(r0), "=r"(r1), "=r"(r2), "=r"(r3)
                    : "r"(addr));
                b[p * 2 + 0][0] = r0; b[p * 2 + 0][1] = r2;
                b[p * 2 + 1][0] = r1; b[p * 2 + 1][1] = r3;
            }
#pragma unroll
            for (int mf = 0; mf < 4; mf++) {
#pragma unroll
                for (int nf = 0; nf < 4; nf++) {
                    float* c = acc[mf][nf];
                    asm volatile(
                        "mma.sync.aligned.m16n8k16.row.col.f32.f16.f16.f32 "
                        "{%0,%1,%2,%3}, {%4,%5,%6,%7}, {%8,%9}, {%0,%1,%2,%3};\n"
                        : "+f"(c[0]), "+f"(c[1]), "+f"(c[2]), "+f"(c[3])
                        : "r"(a[mf][0]), "r"(a[mf][1]), "r"(a[mf][2]), "r"(a[mf][3]),
                          "r"(b[nf][0]), "r"(b[nf][1]));
                }
            }
        }
    }

#pragma unroll
    for (int mf = 0; mf < 4; mf++) {
#pragma unroll
        for (int nf = 0; nf < 4; nf++) {
            int m = m0 + wm * 64 + mf * 16 + (lane >> 2);
            int n = n0 + wn * 32 + nf * 8 + (lane & 3) * 2;
            float2* p0 = reinterpret_cast<float2*>(C + (size_t)m * OUT_F + n);
            *p0 = make_float2(acc[mf][nf][0], acc[mf][nf][1]);
            float2* p1 = reinterpret_cast<float2*>(C + (size_t)(m + 8) * OUT_F + n);
            *p1 = make_float2(acc[mf][nf][2], acc[mf][nf][3]);
        }
    }
}

// ---------------------------------------------------------------------------
extern "C" void kernel_launch(void* const* d_in, const int* in_sizes, int n_in,
                              void* d_out, int out_size) {
    (void)n_in; (void)out_size;
    float* out = (float*)d_out;   // [M, OUT_F] f32

    const int n_x = in_sizes[0];            // x element count (f32)
    const int M   = n_x / IN_F;             // 4096

    // 1) Convert x (f32) -> fp16 g_X
    convert_kernel<<<(n_x / 8 + 255) / 256, 256>>>(
        (const float4*)d_in[0], n_x);

    // 2) Dequantize packed 4-bit weights -> fp16 g_W (f32 scales)
    {
        int total = OUT_F * (IN_F / 8);
        dequant_kernel<<<(total + 255) / 256, 256>>>(
            (const int4*)d_in[1], (const float*)d_in[2], (const int*)d_in[3]);
    }

    // 3) Tensor-core GEMM
    cudaFuncSetAttribute(gemm_kernel,
                         cudaFuncAttributeMaxDynamicSharedMemorySize,
                         STAGES * STAGE_BYTES);
    dim3 grid(M / BM, OUT_F / BN);   // (32, 86): M fastest -> N-band L2 reuse
    gemm_kernel<<<grid, 256, STAGES * STAGE_BYTES>>>(out);
}

// round 6
// speedup vs baseline: 1.1033x; 1.1033x over previous
#include <cuda_runtime.h>
#include <cuda_fp16.h>
#include <cstdint>

// Problem constants (fixed by the dataset)
#define IN_F   4096
#define OUT_F  11008
#define GROUPS 32       // IN_F / 128
#define BM 128
#define BN 256
#define BK 64           // halves per k-tile (128 bytes per row)
#define STAGES 4
#define STAGE_A_BYTES (BM * 128)                   // 16384
#define STAGE_B_BYTES (BN * 128)                   // 32768
#define STAGE_BYTES   (STAGE_A_BYTES + STAGE_B_BYTES)  // 49152
#define KT (IN_F / BK)  // 64

// Dequantized weights, fp16, [OUT_F][IN_F] row-major (K contiguous).
__device__ __half g_W[(size_t)OUT_F * IN_F];
// Activations converted to fp16, [M][IN_F].
__device__ __half g_X[(size_t)4096 * IN_F];

// ---------------------------------------------------------------------------
// Convert x (float32, fp16-valued) -> fp16 in g_X. 8 elements / thread.
// ---------------------------------------------------------------------------
__global__ void convert_kernel(const float4* __restrict__ xin, int n) {
    int i = (blockIdx.x * blockDim.x + threadIdx.x) * 8;
    if (i >= n) return;
    float4 a = xin[i / 4];
    float4 b = xin[i / 4 + 1];
    __half2 h[4];
    h[0] = __floats2half2_rn(a.x, a.y);
    h[1] = __floats2half2_rn(a.z, a.w);
    h[2] = __floats2half2_rn(b.x, b.y);
    h[3] = __floats2half2_rn(b.z, b.w);
    *reinterpret_cast<uint4*>(g_X + i) = *reinterpret_cast<uint4*>(h);
}

// ---------------------------------------------------------------------------
// Dequant: qweight [O][K/2] int32 (one byte/word, two nibbles, low first)
//          qzeros  [O][GROUPS/2] int32, scales [O][GROUPS] float32
// Each thread: 4 packed int32 -> 8 fp16 weights (one uint4 store).
// ---------------------------------------------------------------------------
__global__ void dequant_kernel(const int4* __restrict__ qw,
                               const float* __restrict__ scales,
                               const int* __restrict__ qz) {
    const int JP = IN_F / 8;  // 512 int4-chunks per output row
    int idx = blockIdx.x * blockDim.x + threadIdx.x;
    if (idx >= OUT_F * JP) return;

    int o  = idx / JP;
    int jq = idx - o * JP;
    int g  = jq >> 4;           // group = (jq*8)/128

    int4 v = qw[idx];
    int zb = qz[o * (GROUPS / 2) + (g >> 1)];
    int z  = (g & 1) ? ((zb >> 4) & 15) : (zb & 15);
    float s = scales[o * GROUPS + g];

    int q[4] = {v.x, v.y, v.z, v.w};
    __half2 h[4];
#pragma unroll
    for (int t = 0; t < 4; t++) {
        float w0 = (float)((q[t] & 15) - z) * s;
        float w1 = (float)(((q[t] >> 4) & 15) - z) * s;
        h[t] = __floats2half2_rn(w0, w1);
    }
    *reinterpret_cast<uint4*>(g_W + (size_t)idx * 8) = *reinterpret_cast<uint4*>(h);
}

// ---------------------------------------------------------------------------
// GEMM: C[M][OUT_F] (f32) = A[M][IN_F] (f16) * W^T
// TN mma.sync.m16n8k16. BM=128 BN=256 BK=64, 4-stage cp.async,
// SW128-swizzled smem, 8 warps (2x4), warp tile 64x64.
// ---------------------------------------------------------------------------
__device__ __forceinline__ uint32_t sw128(uint32_t o) {
    return o ^ ((o >> 3) & 0x70);
}

__device__ __forceinline__ void cp_async16(uint32_t saddr, const void* gptr) {
    asm volatile("cp.async.cg.shared.global [%0], [%1], 16;\n"
                 :: "r"(saddr), "l"(gptr) : "memory");
}

// Load one k-stage: A 128x64h (1024 16B chunks) + B 256x64h (2048). 256 thr.
__device__ __forceinline__ void load_tiles(uint32_t sA,
                                           const __half* __restrict__ Ag,
                                           const __half* __restrict__ Bg,
                                           int m0, int n0, int k0, int tid) {
    uint32_t sB = sA + STAGE_A_BYTES;
#pragma unroll
    for (int i = 0; i < 4; i++) {
        int chunk = tid + i * 256;
        int r = chunk >> 3;
        int c = chunk & 7;
        cp_async16(sA + sw128((uint32_t)(r * 128 + c * 16)),
                   Ag + (size_t)(m0 + r) * IN_F + k0 + c * 8);
    }
#pragma unroll
    for (int i = 0; i < 8; i++) {
        int chunk = tid + i * 256;
        int r = chunk >> 3;
        int c = chunk & 7;
        cp_async16(sB + sw128((uint32_t)(r * 128 + c * 16)),
                   Bg + (size_t)(n0 + r) * IN_F + k0 + c * 8);
    }
}

__global__ void __launch_bounds__(256, 1)
gemm_kernel(float* __restrict__ C) {
    extern __shared__ char smem[];
    const __half* __restrict__ A = g_X;
    const __half* __restrict__ B = g_W;

    const int tid  = threadIdx.x;
    const int lane = tid & 31;
    const int warp = tid >> 5;
    const int wm   = warp & 1;     // 0..1 -> m offset wm*64
    const int wn   = warp >> 1;    // 0..3 -> n offset wn*64
    const int m0   = blockIdx.x * BM;
    const int n0   = blockIdx.y * BN;

    uint32_t sbase = (uint32_t)__cvta_generic_to_shared(smem);

    float acc[4][8][4];
#pragma unroll
    for (int i = 0; i < 4; i++)
#pragma unroll
        for (int j = 0; j < 8; j++)
#pragma unroll
            for (int k = 0; k < 4; k++) acc[i][j][k] = 0.0f;

#pragma unroll
    for (int s = 0; s < STAGES - 1; s++) {
        load_tiles(sbase + s * STAGE_BYTES, A, B, m0, n0, s * BK, tid);
        asm volatile("cp.async.commit_group;\n" ::: "memory");
    }

    for (int kt = 0; kt < KT; kt++) {
        asm volatile("cp.async.wait_group 2;\n" ::: "memory");
        __syncthreads();

        int kn = kt + STAGES - 1;
        if (kn < KT) {
            load_tiles(sbase + (kn % STAGES) * STAGE_BYTES, A, B,
                       m0, n0, kn * BK, tid);
        }
        asm volatile("cp.async.commit_group;\n" ::: "memory");

        uint32_t sA = sbase + (kt % STAGES) * STAGE_BYTES;
        uint32_t sB = sA + STAGE_A_BYTES;

#pragma unroll
        for (int ks = 0; ks < 4; ks++) {
            uint32_t a[4][4];
            uint32_t b[8][2];
            const int cb = ks * 32 + ((lane >> 4) << 4);  // byte col in 128B row

#pragma unroll
            for (int mf = 0; mf < 4; mf++) {
                int r = wm * 64 + mf * 16 + (lane & 15);
                uint32_t addr = sA + sw128((uint32_t)(r * 128 + cb));
                asm volatile(
                    "ldmatrix.sync.aligned.m8n8.x4.shared.b16 {%0,%1,%2,%3}, [%4];\n"
                    : "=r"(a[mf][0]), "=r"(a[mf][1]), "=r"(a[mf][2]), "=r"(a[mf][3])
                    : "r"(addr));
            }
#pragma unroll
            for (int p = 0; p < 4; p++) {
                int r = wn * 64 + p * 16 + (lane & 15);
                uint32_t addr = sB + sw128((uint32_t)(r * 128 + cb));
                uint32_t r0, r1, r2, r3;
                asm volatile(
                    "ldmatrix.sync.aligned.m8n8.x4.shared.b16 {%0,%1,%2,%3}, [%4];\n"
                    : "=r"(r0), "=r"(r1), "=r"(r2), "=r"(r3)
                    : "r"(addr));
                // reg0: n[0..7] k[0..7], reg1: n[8..15] k[0..7],
                // reg2: n[0..7] k[8..15], reg3: n[8..15] k[8..15]
                b[p * 2 + 0][0] = r0; b[p * 2 + 0][1] = r2;
                b[p * 2 + 1][0] = r1; b[p * 2 + 1][1] = r3;
            }
#pragma unroll
            for (int mf = 0; mf < 4; mf++) {
#pragma unroll
                for (int nf = 0; nf < 8; nf++) {
                    float* c = acc[mf][nf];
                    asm volatile(
                        "mma.sync.aligned.m16n8k16.row.col.f32.f16.f16.f32 "
                        "{%0,%1,%2,%3}, {%4,%5,%6,%7}, {%8,%9}, {%0,%1,%2,%3};\n"
                        : "+f"(c[0]), "+f"(c[1]), "+f"(c[2]), "+f"(c[3])
                        : "r"(a[mf][0]), "r"(a[mf][1]), "r"(a[mf][2]), "r"(a[mf][3]),
                          "r"(b[nf][0]), "r"(b[nf][1]));
                }
            }
        }
    }

    // Epilogue: direct f32 stores (float2), every element covered.
#pragma unroll
    for (int mf = 0; mf < 4; mf++) {
#pragma unroll
        for (int nf = 0; nf < 8; nf++) {
            int m = m0 + wm * 64 + mf * 16 + (lane >> 2);
            int n = n0 + wn * 64 + nf * 8 + (lane & 3) * 2;
            float2* p0 = reinterpret_cast<float2*>(C + (size_t)m * OUT_F + n);
            *p0 = make_float2(acc[mf][nf][0], acc[mf][nf][1]);
            float2* p1 = reinterpret_cast<float2*>(C + (size_t)(m + 8) * OUT_F + n);
            *p1 = make_float2(acc[mf][nf][2], acc[mf][nf][3]);
        }
    }
}

// ---------------------------------------------------------------------------
extern "C" void kernel_launch(void* const* d_in, const int* in_sizes, int n_in,
                              void* d_out, int out_size) {
    (void)n_in; (void)out_size;
    float* out = (float*)d_out;   // [M, OUT_F] f32

    const int n_x = in_sizes[0];            // x element count (f32)
    const int M   = n_x / IN_F;             // 4096

    // 1) Convert x (f32) -> fp16 g_X
    convert_kernel<<<(n_x / 8 + 255) / 256, 256>>>(
        (const float4*)d_in[0], n_x);

    // 2) Dequantize packed 4-bit weights -> fp16 g_W (f32 scales)
    {
        int total = OUT_F * (IN_F / 8);
        dequant_kernel<<<(total + 255) / 256, 256>>>(
            (const int4*)d_in[1], (const float*)d_in[2], (const int*)d_in[3]);
    }

    // 3) Tensor-core GEMM
    cudaFuncSetAttribute(gemm_kernel,
                         cudaFuncAttributeMaxDynamicSharedMemorySize,
                         STAGES * STAGE_BYTES);
    dim3 grid(M / BM, OUT_F / BN);   // (32, 43): M fastest -> N-band L2 reuse
    gemm_kernel<<<grid, 256, STAGES * STAGE_BYTES>>>(out);
}

// round 7
// speedup vs baseline: 1.2156x; 1.1018x over previous
#include <cuda_runtime.h>
#include <cuda_fp16.h>
#include <cstdint>

// Problem constants (fixed by the dataset)
#define IN_F   4096
#define OUT_F  11008
#define GROUPS 32       // IN_F / 128
#define BM 128
#define BN 128
#define BK 64           // halves per k-tile (128 bytes per row)
#define STAGES 3
#define STAGE_A_BYTES (BM * 128)                       // 16384
#define STAGE_B_BYTES (BN * 128)                       // 16384
#define STAGE_BYTES   (STAGE_A_BYTES + STAGE_B_BYTES)  // 32768
#define KT (IN_F / BK)  // 64

// Dequantized weights, fp16, [OUT_F][IN_F] row-major (K contiguous).
__device__ __half g_W[(size_t)OUT_F * IN_F];
// Activations converted to fp16, [M][IN_F].
__device__ __half g_X[(size_t)4096 * IN_F];

// ---------------------------------------------------------------------------
// Convert x (float32, fp16-valued) -> fp16 in g_X. 8 elements / thread.
// ---------------------------------------------------------------------------
__global__ void convert_kernel(const float4* __restrict__ xin, int n) {
    int i = (blockIdx.x * blockDim.x + threadIdx.x) * 8;
    if (i >= n) return;
    float4 a = xin[i / 4];
    float4 b = xin[i / 4 + 1];
    __half2 h[4];
    h[0] = __floats2half2_rn(a.x, a.y);
    h[1] = __floats2half2_rn(a.z, a.w);
    h[2] = __floats2half2_rn(b.x, b.y);
    h[3] = __floats2half2_rn(b.z, b.w);
    *reinterpret_cast<uint4*>(g_X + i) = *reinterpret_cast<uint4*>(h);
}

// ---------------------------------------------------------------------------
// Dequant: qweight [O][K/2] int32 (one byte/word, two nibbles, low first)
//          qzeros  [O][GROUPS/2] int32, scales [O][GROUPS] float32
// Each thread: 4 packed int32 -> 8 fp16 weights (one uint4 store).
// ---------------------------------------------------------------------------
__global__ void dequant_kernel(const int4* __restrict__ qw,
                               const float* __restrict__ scales,
                               const int* __restrict__ qz) {
    const int JP = IN_F / 8;  // 512 int4-chunks per output row
    int idx = blockIdx.x * blockDim.x + threadIdx.x;
    if (idx >= OUT_F * JP) return;

    int o  = idx / JP;
    int jq = idx - o * JP;
    int g  = jq >> 4;           // group = (jq*8)/128

    int4 v = qw[idx];
    int zb = qz[o * (GROUPS / 2) + (g >> 1)];
    int z  = (g & 1) ? ((zb >> 4) & 15) : (zb & 15);
    float s = scales[o * GROUPS + g];

    int q[4] = {v.x, v.y, v.z, v.w};
    __half2 h[4];
#pragma unroll
    for (int t = 0; t < 4; t++) {
        float w0 = (float)((q[t] & 15) - z) * s;
        float w1 = (float)(((q[t] >> 4) & 15) - z) * s;
        h[t] = __floats2half2_rn(w0, w1);
    }
    *reinterpret_cast<uint4*>(g_W + (size_t)idx * 8) = *reinterpret_cast<uint4*>(h);
}

// ---------------------------------------------------------------------------
// GEMM: C[M][OUT_F] (f32) = A[M][IN_F] (f16) * W^T
// TN mma.sync.m16n8k16. BM=BN=128 BK=64, 3-stage cp.async, SW128 smem,
// 4 warps (2x2), warp tile 64x64, 2 CTAs/SM, reg-level fragment pipelining.
// ---------------------------------------------------------------------------
__device__ __forceinline__ uint32_t sw128(uint32_t o) {
    return o ^ ((o >> 3) & 0x70);
}

__device__ __forceinline__ void cp_async16(uint32_t saddr, const void* gptr) {
    asm volatile("cp.async.cg.shared.global [%0], [%1], 16;\n"
                 :: "r"(saddr), "l"(gptr) : "memory");
}

// Load one k-stage: A 128x64h (1024 16B chunks) + B 128x64h (1024). 128 thr.
__device__ __forceinline__ void load_tiles(uint32_t sA,
                                           const __half* __restrict__ Ag,
                                           const __half* __restrict__ Bg,
                                           int m0, int n0, int k0, int tid) {
    uint32_t sB = sA + STAGE_A_BYTES;
#pragma unroll
    for (int i = 0; i < 8; i++) {
        int chunk = tid + i * 128;
        int r = chunk >> 3;
        int c = chunk & 7;
        cp_async16(sA + sw128((uint32_t)(r * 128 + c * 16)),
                   Ag + (size_t)(m0 + r) * IN_F + k0 + c * 8);
    }
#pragma unroll
    for (int i = 0; i < 8; i++) {
        int chunk = tid + i * 128;
        int r = chunk >> 3;
        int c = chunk & 7;
        cp_async16(sB + sw128((uint32_t)(r * 128 + c * 16)),
                   Bg + (size_t)(n0 + r) * IN_F + k0 + c * 8);
    }
}

// Load one ks-step's register fragments (a: 4 x ldmatrix.x4, b: 4 x ldmatrix.x4)
__device__ __forceinline__ void load_frags(uint32_t sA, uint32_t sB, int ks,
                                           int wm, int wn, int lane,
                                           uint32_t a[4][4], uint32_t b[8][2]) {
    const int cb = ks * 32 + ((lane >> 4) << 4);  // byte col within 128B row
#pragma unroll
    for (int mf = 0; mf < 4; mf++) {
        int r = wm * 64 + mf * 16 + (lane & 15);
        uint32_t addr = sA + sw128((uint32_t)(r * 128 + cb));
        asm volatile(
            "ldmatrix.sync.aligned.m8n8.x4.shared.b16 {%0,%1,%2,%3}, [%4];\n"
            : "=r"(a[mf][0]), "=r"(a[mf][1]), "=r"(a[mf][2]), "=r"(a[mf][3])
            : "r"(addr));
    }
#pragma unroll
    for (int p = 0; p < 4; p++) {
        int r = wn * 64 + p * 16 + (lane & 15);
        uint32_t addr = sB + sw128((uint32_t)(r * 128 + cb));
        uint32_t r0, r1, r2, r3;
        asm volatile(
            "ldmatrix.sync.aligned.m8n8.x4.shared.b16 {%0,%1,%2,%3}, [%4];\n"
            : "=r"(r0), "=r"(r1), "=r"(r2), "=r"(r3)
            : "r"(addr));
        // reg0: n[0..7] k[0..7], reg1: n[8..15] k[0..7],
        // reg2: n[0..7] k[8..15], reg3: n[8..15] k[8..15]
        b[p * 2 + 0][0] = r0; b[p * 2 + 0][1] = r2;
        b[p * 2 + 1][0] = r1; b[p * 2 + 1][1] = r3;
    }
}

__global__ void __launch_bounds__(128, 2)
gemm_kernel(float* __restrict__ C) {
    extern __shared__ char smem[];
    const __half* __restrict__ A = g_X;
    const __half* __restrict__ B = g_W;

    const int tid  = threadIdx.x;
    const int lane = tid & 31;
    const int warp = tid >> 5;
    const int wm   = warp & 1;     // 0..1 -> m offset wm*64
    const int wn   = warp >> 1;    // 0..1 -> n offset wn*64
    const int m0   = blockIdx.x * BM;
    const int n0   = blockIdx.y * BN;

    uint32_t sbase = (uint32_t)__cvta_generic_to_shared(smem);

    float acc[4][8][4];
#pragma unroll
    for (int i = 0; i < 4; i++)
#pragma unroll
        for (int j = 0; j < 8; j++)
#pragma unroll
            for (int k = 0; k < 4; k++) acc[i][j][k] = 0.0f;

#pragma unroll
    for (int s = 0; s < STAGES - 1; s++) {
        load_tiles(sbase + s * STAGE_BYTES, A, B, m0, n0, s * BK, tid);
        asm volatile("cp.async.commit_group;\n" ::: "memory");
    }

    uint32_t a[2][4][4];
    uint32_t b[2][8][2];

    for (int kt = 0; kt < KT; kt++) {
        asm volatile("cp.async.wait_group 1;\n" ::: "memory");
        __syncthreads();

        int kn = kt + STAGES - 1;
        if (kn < KT) {
            load_tiles(sbase + (kn % STAGES) * STAGE_BYTES, A, B,
                       m0, n0, kn * BK, tid);
        }
        asm volatile("cp.async.commit_group;\n" ::: "memory");

        uint32_t sA = sbase + (kt % STAGES) * STAGE_BYTES;
        uint32_t sB = sA + STAGE_A_BYTES;

        // Software-pipelined fragments over the 4 ks steps
        load_frags(sA, sB, 0, wm, wn, lane, a[0], b[0]);
#pragma unroll
        for (int ks = 0; ks < 4; ks++) {
            int cur = ks & 1;
            if (ks < 3)
                load_frags(sA, sB, ks + 1, wm, wn, lane, a[cur ^ 1], b[cur ^ 1]);
#pragma unroll
            for (int mf = 0; mf < 4; mf++) {
#pragma unroll
                for (int nf = 0; nf < 8; nf++) {
                    float* c = acc[mf][nf];
                    asm volatile(
                        "mma.sync.aligned.m16n8k16.row.col.f32.f16.f16.f32 "
                        "{%0,%1,%2,%3}, {%4,%5,%6,%7}, {%8,%9}, {%0,%1,%2,%3};\n"
                        : "+f"(c[0]), "+f"(c[1]), "+f"(c[2]), "+f"(c[3])
                        : "r"(a[cur][mf][0]), "r"(a[cur][mf][1]),
                          "r"(a[cur][mf][2]), "r"(a[cur][mf][3]),
                          "r"(b[cur][nf][0]), "r"(b[cur][nf][1]));
                }
            }
        }
    }

    // Epilogue: direct f32 stores (float2), every element covered.
#pragma unroll
    for (int mf = 0; mf < 4; mf++) {
#pragma unroll
        for (int nf = 0; nf < 8; nf++) {
            int m = m0 + wm * 64 + mf * 16 + (lane >> 2);
            int n = n0 + wn * 64 + nf * 8 + (lane & 3) * 2;
            float2* p0 = reinterpret_cast<float2*>(C + (size_t)m * OUT_F + n);
            *p0 = make_float2(acc[mf][nf][0], acc[mf][nf][1]);
            float2* p1 = reinterpret_cast<float2*>(C + (size_t)(m + 8) * OUT_F + n);
            *p1 = make_float2(acc[mf][nf][2], acc[mf][nf][3]);
        }
    }
}

// ---------------------------------------------------------------------------
extern "C" void kernel_launch(void* const* d_in, const int* in_sizes, int n_in,
                              void* d_out, int out_size) {
    (void)n_in; (void)out_size;
    float* out = (float*)d_out;   // [M, OUT_F] f32

    const int n_x = in_sizes[0];            // x element count (f32)
    const int M   = n_x / IN_F;             // 4096

    // 1) Convert x (f32) -> fp16 g_X
    convert_kernel<<<(n_x / 8 + 255) / 256, 256>>>(
        (const float4*)d_in[0], n_x);

    // 2) Dequantize packed 4-bit weights -> fp16 g_W (f32 scales)
    {
        int total = OUT_F * (IN_F / 8);
        dequant_kernel<<<(total + 255) / 256, 256>>>(
            (const int4*)d_in[1], (const float*)d_in[2], (const int*)d_in[3]);
    }

    // 3) Tensor-core GEMM (2 CTAs/SM)
    cudaFuncSetAttribute(gemm_kernel,
                         cudaFuncAttributeMaxDynamicSharedMemorySize,
                         STAGES * STAGE_BYTES);
    dim3 grid(M / BM, OUT_F / BN);   // (32, 86): M fastest -> N-band L2 reuse
    gemm_kernel<<<grid, 128, STAGES * STAGE_BYTES>>>(out);
}